// round 1
// baseline (speedup 1.0000x reference)
#include <cuda_runtime.h>
#include <cstdint>

// Problem constants (fixed by the dataset)
#define NN 500000
#define EE 10000000
#define GG 1000
#define HH 8

// ---------------------------------------------------------------------------
// Scratch (device globals — no cudaMalloc allowed). ~40 MB total.
// ---------------------------------------------------------------------------
__device__ unsigned g_deg_in [NN];
__device__ unsigned g_deg_out[NN];
__device__ float    g_x0   [NN];        // deg_in * inv_sqrt_out  (layer-1 input, pre-scaled)
__device__ float    g_agg1 [NN];        // layer-1 aggregated
__device__ float    g_y1   [NN * HH];   // relu(layer1) * inv_sqrt_out (layer-2 input, pre-scaled)
__device__ float    g_agg2 [NN * HH];   // layer-2 aggregated
__device__ float    g_hg   [GG * HH];   // graph pooled sums
__device__ float    g_cnt  [GG];        // nodes per graph

__device__ __forceinline__ void red_v4(float* p, float a, float b, float c, float d) {
    asm volatile("red.global.add.v4.f32 [%0], {%1, %2, %3, %4};"
                 :: "l"(p), "f"(a), "f"(b), "f"(c), "f"(d) : "memory");
}

// ---------------------------------------------------------------------------
// K1: degree counting. 4 edges / thread via int4 loads for MLP.
// ---------------------------------------------------------------------------
__global__ void k_deg(const int* __restrict__ src, const int* __restrict__ dst, int E) {
    int i = blockIdx.x * blockDim.x + threadIdx.x;
    int base = i << 2;
    if (base + 3 < E) {
        int4 s = *reinterpret_cast<const int4*>(src + base);
        int4 d = *reinterpret_cast<const int4*>(dst + base);
        atomicAdd(&g_deg_out[s.x], 1u); atomicAdd(&g_deg_out[s.y], 1u);
        atomicAdd(&g_deg_out[s.z], 1u); atomicAdd(&g_deg_out[s.w], 1u);
        atomicAdd(&g_deg_in [d.x], 1u); atomicAdd(&g_deg_in [d.y], 1u);
        atomicAdd(&g_deg_in [d.z], 1u); atomicAdd(&g_deg_in [d.w], 1u);
    } else {
        for (int e = base; e < E; ++e) {
            atomicAdd(&g_deg_out[src[e]], 1u);
            atomicAdd(&g_deg_in [dst[e]], 1u);
        }
    }
}

// ---------------------------------------------------------------------------
// K2: x0[n] = deg_in[n] * max(deg_out[n],1)^-0.5
// ---------------------------------------------------------------------------
__global__ void k_x0(int N) {
    int i = blockIdx.x * blockDim.x + threadIdx.x;
    if (i >= N) return;
    float di = (float)g_deg_in[i];
    float dо = (float)g_deg_out[i];
    g_x0[i] = di * rsqrtf(fmaxf(dо, 1.0f));
}

// ---------------------------------------------------------------------------
// K3: layer-1 scatter  agg1[dst] += x0[src].  4 edges / thread.
// ---------------------------------------------------------------------------
__global__ void k_scatter1(const int* __restrict__ src, const int* __restrict__ dst, int E) {
    int i = blockIdx.x * blockDim.x + threadIdx.x;
    int base = i << 2;
    if (base + 3 < E) {
        int4 s = *reinterpret_cast<const int4*>(src + base);
        int4 d = *reinterpret_cast<const int4*>(dst + base);
        float v0 = __ldg(&g_x0[s.x]);
        float v1 = __ldg(&g_x0[s.y]);
        float v2 = __ldg(&g_x0[s.z]);
        float v3 = __ldg(&g_x0[s.w]);
        atomicAdd(&g_agg1[d.x], v0); atomicAdd(&g_agg1[d.y], v1);
        atomicAdd(&g_agg1[d.z], v2); atomicAdd(&g_agg1[d.w], v3);
    } else {
        for (int e = base; e < E; ++e)
            atomicAdd(&g_agg1[dst[e]], __ldg(&g_x0[src[e]]));
    }
}

// ---------------------------------------------------------------------------
// K4: layer-1 node update.  s = agg1*inv_sqrt_in;  h1_j = relu(s * W1_j);
//     y1 = h1 * inv_sqrt_out (pre-scale for the layer-2 propagation).
// ---------------------------------------------------------------------------
__global__ void k_node1(const float* __restrict__ W1, int N) {
    int i = blockIdx.x * blockDim.x + threadIdx.x;
    if (i >= N) return;
    float s   = g_agg1[i] * rsqrtf(fmaxf((float)g_deg_in[i],  1.0f));
    float iso = rsqrtf(fmaxf((float)g_deg_out[i], 1.0f));
    float4 a, b;
    a.x = fmaxf(s * __ldg(&W1[0]), 0.0f) * iso;
    a.y = fmaxf(s * __ldg(&W1[1]), 0.0f) * iso;
    a.z = fmaxf(s * __ldg(&W1[2]), 0.0f) * iso;
    a.w = fmaxf(s * __ldg(&W1[3]), 0.0f) * iso;
    b.x = fmaxf(s * __ldg(&W1[4]), 0.0f) * iso;
    b.y = fmaxf(s * __ldg(&W1[5]), 0.0f) * iso;
    b.z = fmaxf(s * __ldg(&W1[6]), 0.0f) * iso;
    b.w = fmaxf(s * __ldg(&W1[7]), 0.0f) * iso;
    float4* yp = reinterpret_cast<float4*>(g_y1);
    yp[2 * i]     = a;
    yp[2 * i + 1] = b;
}

// ---------------------------------------------------------------------------
// K5: layer-2 scatter  agg2[dst][:] += y1[src][:]  (8 floats / edge)
//     One edge / thread; two red.global.add.v4.f32 per edge.
// ---------------------------------------------------------------------------
__global__ void k_scatter2(const int* __restrict__ src, const int* __restrict__ dst, int E) {
    int i = blockIdx.x * blockDim.x + threadIdx.x;
    if (i >= E) return;
    int s = src[i];
    int d = dst[i];
    const float4* yp = reinterpret_cast<const float4*>(g_y1);
    float4 a = __ldg(&yp[2 * s]);
    float4 b = __ldg(&yp[2 * s + 1]);
    float* p = g_agg2 + (size_t)d * HH;
    red_v4(p,     a.x, a.y, a.z, a.w);
    red_v4(p + 4, b.x, b.y, b.z, b.w);
}

// ---------------------------------------------------------------------------
// K6: layer-2 node update + graph pooling.
//     h2 = relu((agg2 * inv_sqrt_in) @ W2); hg[g] += h2; cnt[g] += 1.
//     graph_ids is sorted -> warp-uniform fast path (shuffle tree reduce,
//     lane 0 emits 2x red.v4 + 1 scalar RED).
// ---------------------------------------------------------------------------
__global__ void k_node2_pool(const float* __restrict__ W2, const int* __restrict__ gid, int N) {
    __shared__ float sW[64];
    if (threadIdx.x < 64) sW[threadIdx.x] = W2[threadIdx.x];
    __syncthreads();

    int i = blockIdx.x * blockDim.x + threadIdx.x;
    bool valid = (i < N);

    float h[8];
    int g = -1;
    if (valid) {
        const float4* ap = reinterpret_cast<const float4*>(g_agg2);
        float4 a = ap[2 * i];
        float4 b = ap[2 * i + 1];
        float isi = rsqrtf(fmaxf((float)g_deg_in[i], 1.0f));
        float v0 = a.x, v1 = a.y, v2 = a.z, v3 = a.w;
        float v4 = b.x, v5 = b.y, v6 = b.z, v7 = b.w;
#pragma unroll
        for (int j = 0; j < 8; ++j) {
            float acc = v0 * sW[0 * 8 + j] + v1 * sW[1 * 8 + j]
                      + v2 * sW[2 * 8 + j] + v3 * sW[3 * 8 + j]
                      + v4 * sW[4 * 8 + j] + v5 * sW[5 * 8 + j]
                      + v6 * sW[6 * 8 + j] + v7 * sW[7 * 8 + j];
            h[j] = fmaxf(acc * isi, 0.0f);
        }
        g = gid[i];
    } else {
#pragma unroll
        for (int j = 0; j < 8; ++j) h[j] = 0.0f;
    }

    int  g0  = __shfl_sync(0xffffffffu, g, 0);
    bool uni = __all_sync(0xffffffffu, g == g0);

    if (uni && g0 >= 0) {
#pragma unroll
        for (int j = 0; j < 8; ++j) {
#pragma unroll
            for (int o = 16; o > 0; o >>= 1)
                h[j] += __shfl_xor_sync(0xffffffffu, h[j], o);
        }
        if ((threadIdx.x & 31) == 0) {
            float* p = g_hg + g0 * HH;
            red_v4(p,     h[0], h[1], h[2], h[3]);
            red_v4(p + 4, h[4], h[5], h[6], h[7]);
            atomicAdd(&g_cnt[g0], 32.0f);
        }
    } else if (valid) {
        float* p = g_hg + g * HH;
        red_v4(p,     h[0], h[1], h[2], h[3]);
        red_v4(p + 4, h[4], h[5], h[6], h[7]);
        atomicAdd(&g_cnt[g], 1.0f);
    }
}

// ---------------------------------------------------------------------------
// K7: out[g][c] = (hg[g]/max(cnt,1)) . Wlast[:,c]
// ---------------------------------------------------------------------------
__global__ void k_final(const float* __restrict__ Wlast, float* __restrict__ out, int G) {
    int t = blockIdx.x * blockDim.x + threadIdx.x;
    if (t >= G * 8) return;
    int g = t >> 3;
    int c = t & 7;
    float inv = 1.0f / fmaxf(g_cnt[g], 1.0f);
    float acc = 0.0f;
#pragma unroll
    for (int k = 0; k < 8; ++k)
        acc += g_hg[g * 8 + k] * Wlast[k * 8 + c];
    out[t] = acc * inv;
}

// ---------------------------------------------------------------------------
// kernel_launch — graph-capturable, allocation-free.
// Inputs (metadata order): W1[8], W2[64], Wlast[64], src[E], dst[E], graph_ids[N]
// Output: G*C float32
// ---------------------------------------------------------------------------
extern "C" void kernel_launch(void* const* d_in, const int* in_sizes, int n_in,
                              void* d_out, int out_size) {
    const float* W1    = (const float*)d_in[0];
    const float* W2    = (const float*)d_in[1];
    const float* Wlast = (const float*)d_in[2];
    const int*   src   = (const int*)d_in[3];
    const int*   dst   = (const int*)d_in[4];
    const int*   gid   = (const int*)d_in[5];

    int E = in_sizes[3];
    int N = in_sizes[5];
    int G = out_size / 8;
    float* out = (float*)d_out;

    // Zero the accumulators (captured as memset nodes).
    void *pdi, *pdo, *pa1, *pa2, *phg, *pcnt;
    cudaGetSymbolAddress(&pdi,  g_deg_in);
    cudaGetSymbolAddress(&pdo,  g_deg_out);
    cudaGetSymbolAddress(&pa1,  g_agg1);
    cudaGetSymbolAddress(&pa2,  g_agg2);
    cudaGetSymbolAddress(&phg,  g_hg);
    cudaGetSymbolAddress(&pcnt, g_cnt);
    cudaMemsetAsync(pdi,  0, (size_t)N * sizeof(unsigned));
    cudaMemsetAsync(pdo,  0, (size_t)N * sizeof(unsigned));
    cudaMemsetAsync(pa1,  0, (size_t)N * sizeof(float));
    cudaMemsetAsync(pa2,  0, (size_t)N * HH * sizeof(float));
    cudaMemsetAsync(phg,  0, (size_t)G * HH * sizeof(float));
    cudaMemsetAsync(pcnt, 0, (size_t)G * sizeof(float));

    const int TB = 256;
    int nE4 = (E + 3) / 4;
    int gE4 = (nE4 + TB - 1) / TB;
    int gN  = (N + TB - 1) / TB;
    int gE  = (E + TB - 1) / TB;

    k_deg      <<<gE4, TB>>>(src, dst, E);
    k_x0       <<<gN,  TB>>>(N);
    k_scatter1 <<<gE4, TB>>>(src, dst, E);
    k_node1    <<<gN,  TB>>>(W1, N);
    k_scatter2 <<<gE,  TB>>>(src, dst, E);
    k_node2_pool<<<gN, TB>>>(W2, gid, N);
    k_final    <<<(G * 8 + TB - 1) / TB, TB>>>(Wlast, out, G);
}

// round 2
// speedup vs baseline: 1.2296x; 1.2296x over previous
#include <cuda_runtime.h>
#include <cstdint>

// Problem constants (fixed by the dataset)
#define NN 500000
#define GG 1000

// ---------------------------------------------------------------------------
// Scratch (device globals). Rank-1 collapse: everything is scalar per node.
// ---------------------------------------------------------------------------
__device__ unsigned g_deg_in [NN];
__device__ unsigned g_deg_out[NN];
__device__ float    g_x0  [NN];     // deg_in * inv_sqrt_out
__device__ float    g_agg1[NN];     // layer-1 scalar aggregation
__device__ float    g_t   [NN];     // s * inv_sqrt_out (layer-2 propagand)
__device__ float    g_A   [NN];     // layer-2 scalar aggregation
__device__ float    g_S   [GG];     // pooled scalar sum per graph
__device__ float    g_cnt [GG];     // nodes per graph

__device__ __forceinline__ void red_f32(float* p, float v) {
    asm volatile("red.global.add.f32 [%0], %1;" :: "l"(p), "f"(v) : "memory");
}
__device__ __forceinline__ void red_u32(unsigned* p, unsigned v) {
    asm volatile("red.global.add.u32 [%0], %1;" :: "l"(p), "r"(v) : "memory");
}

// ---------------------------------------------------------------------------
// K1: degree counting. 4 edges / thread via int4 loads for MLP.
// ---------------------------------------------------------------------------
__global__ void k_deg(const int* __restrict__ src, const int* __restrict__ dst, int E) {
    int i = blockIdx.x * blockDim.x + threadIdx.x;
    int base = i << 2;
    if (base + 3 < E) {
        int4 s = *reinterpret_cast<const int4*>(src + base);
        int4 d = *reinterpret_cast<const int4*>(dst + base);
        red_u32(&g_deg_out[s.x], 1u); red_u32(&g_deg_out[s.y], 1u);
        red_u32(&g_deg_out[s.z], 1u); red_u32(&g_deg_out[s.w], 1u);
        red_u32(&g_deg_in [d.x], 1u); red_u32(&g_deg_in [d.y], 1u);
        red_u32(&g_deg_in [d.z], 1u); red_u32(&g_deg_in [d.w], 1u);
    } else {
        for (int e = base; e < E; ++e) {
            red_u32(&g_deg_out[src[e]], 1u);
            red_u32(&g_deg_in [dst[e]], 1u);
        }
    }
}

// ---------------------------------------------------------------------------
// K2: x0[n] = deg_in[n] * max(deg_out[n],1)^-0.5
// ---------------------------------------------------------------------------
__global__ void k_x0(int N) {
    int i = blockIdx.x * blockDim.x + threadIdx.x;
    if (i >= N) return;
    float di = (float)g_deg_in[i];
    float dq = (float)g_deg_out[i];
    g_x0[i] = di * rsqrtf(fmaxf(dq, 1.0f));
}

// ---------------------------------------------------------------------------
// K3: layer-1 scalar scatter  agg1[dst] += x0[src].  4 edges / thread.
// ---------------------------------------------------------------------------
__global__ void k_scatter1(const int* __restrict__ src, const int* __restrict__ dst, int E) {
    int i = blockIdx.x * blockDim.x + threadIdx.x;
    int base = i << 2;
    if (base + 3 < E) {
        int4 s = *reinterpret_cast<const int4*>(src + base);
        int4 d = *reinterpret_cast<const int4*>(dst + base);
        float v0 = __ldg(&g_x0[s.x]);
        float v1 = __ldg(&g_x0[s.y]);
        float v2 = __ldg(&g_x0[s.z]);
        float v3 = __ldg(&g_x0[s.w]);
        red_f32(&g_agg1[d.x], v0); red_f32(&g_agg1[d.y], v1);
        red_f32(&g_agg1[d.z], v2); red_f32(&g_agg1[d.w], v3);
    } else {
        for (int e = base; e < E; ++e)
            red_f32(&g_agg1[dst[e]], __ldg(&g_x0[src[e]]));
    }
}

// ---------------------------------------------------------------------------
// K4: t[n] = agg1[n] * inv_sqrt_in[n] * inv_sqrt_out[n]
//     (= s_n * iso_n; the scalar field propagated in layer 2)
// ---------------------------------------------------------------------------
__global__ void k_t(int N) {
    int i = blockIdx.x * blockDim.x + threadIdx.x;
    if (i >= N) return;
    float isi = rsqrtf(fmaxf((float)g_deg_in [i], 1.0f));
    float iso = rsqrtf(fmaxf((float)g_deg_out[i], 1.0f));
    g_t[i] = g_agg1[i] * isi * iso;
}

// ---------------------------------------------------------------------------
// K5: layer-2 scalar scatter  A[dst] += t[src].  4 edges / thread.
// ---------------------------------------------------------------------------
__global__ void k_scatter2(const int* __restrict__ src, const int* __restrict__ dst, int E) {
    int i = blockIdx.x * blockDim.x + threadIdx.x;
    int base = i << 2;
    if (base + 3 < E) {
        int4 s = *reinterpret_cast<const int4*>(src + base);
        int4 d = *reinterpret_cast<const int4*>(dst + base);
        float v0 = __ldg(&g_t[s.x]);
        float v1 = __ldg(&g_t[s.y]);
        float v2 = __ldg(&g_t[s.z]);
        float v3 = __ldg(&g_t[s.w]);
        red_f32(&g_A[d.x], v0); red_f32(&g_A[d.y], v1);
        red_f32(&g_A[d.z], v2); red_f32(&g_A[d.w], v3);
    } else {
        for (int e = base; e < E; ++e)
            red_f32(&g_A[dst[e]], __ldg(&g_t[src[e]]));
    }
}

// ---------------------------------------------------------------------------
// K6: scalar pooling.  u = A * inv_sqrt_in;  S[g] += u; cnt[g] += 1.
//     graph_ids sorted -> warp-uniform fast path (1 RED per warp).
// ---------------------------------------------------------------------------
__global__ void k_pool(const int* __restrict__ gid, int N) {
    int i = blockIdx.x * blockDim.x + threadIdx.x;
    bool valid = (i < N);
    float u = 0.0f;
    int g = -1;
    if (valid) {
        u = g_A[i] * rsqrtf(fmaxf((float)g_deg_in[i], 1.0f));
        g = gid[i];
    }
    int  g0  = __shfl_sync(0xffffffffu, g, 0);
    bool uni = __all_sync(0xffffffffu, valid && (g == g0));
    if (uni) {
#pragma unroll
        for (int o = 16; o > 0; o >>= 1)
            u += __shfl_xor_sync(0xffffffffu, u, o);
        if ((threadIdx.x & 31) == 0) {
            red_f32(&g_S[g0], u);
            red_f32(&g_cnt[g0], 32.0f);
        }
    } else if (valid) {
        red_f32(&g_S[g], u);
        red_f32(&g_cnt[g], 1.0f);
    }
}

// ---------------------------------------------------------------------------
// K7: out[g][c] = (S_g / max(cnt_g,1)) * rW_c
//     rW_c = relu(relu(W1) @ W2) @ Wlast[:,c]   (computed per-thread, tiny)
// ---------------------------------------------------------------------------
__global__ void k_final(const float* __restrict__ W1, const float* __restrict__ W2,
                        const float* __restrict__ Wlast, float* __restrict__ out, int G) {
    int t = blockIdx.x * blockDim.x + threadIdx.x;
    if (t >= G * 8) return;
    int g = t >> 3;
    int c = t & 7;
    float rw = 0.0f;
#pragma unroll
    for (int k = 0; k < 8; ++k) {
        float q = 0.0f;
#pragma unroll
        for (int j = 0; j < 8; ++j)
            q += fmaxf(__ldg(&W1[j]), 0.0f) * __ldg(&W2[j * 8 + k]);
        rw += fmaxf(q, 0.0f) * __ldg(&Wlast[k * 8 + c]);
    }
    out[t] = (g_S[g] / fmaxf(g_cnt[g], 1.0f)) * rw;
}

// ---------------------------------------------------------------------------
// kernel_launch — graph-capturable, allocation-free.
// Inputs (metadata order): W1[8], W2[64], Wlast[64], src[E], dst[E], graph_ids[N]
// Output: G*C float32
// ---------------------------------------------------------------------------
extern "C" void kernel_launch(void* const* d_in, const int* in_sizes, int n_in,
                              void* d_out, int out_size) {
    const float* W1    = (const float*)d_in[0];
    const float* W2    = (const float*)d_in[1];
    const float* Wlast = (const float*)d_in[2];
    const int*   src   = (const int*)d_in[3];
    const int*   dst   = (const int*)d_in[4];
    const int*   gid   = (const int*)d_in[5];

    int E = in_sizes[3];
    int N = in_sizes[5];
    int G = out_size / 8;
    float* out = (float*)d_out;

    void *pdi, *pdo, *pa1, *pA, *pS, *pcnt;
    cudaGetSymbolAddress(&pdi,  g_deg_in);
    cudaGetSymbolAddress(&pdo,  g_deg_out);
    cudaGetSymbolAddress(&pa1,  g_agg1);
    cudaGetSymbolAddress(&pA,   g_A);
    cudaGetSymbolAddress(&pS,   g_S);
    cudaGetSymbolAddress(&pcnt, g_cnt);
    cudaMemsetAsync(pdi,  0, (size_t)N * sizeof(unsigned));
    cudaMemsetAsync(pdo,  0, (size_t)N * sizeof(unsigned));
    cudaMemsetAsync(pa1,  0, (size_t)N * sizeof(float));
    cudaMemsetAsync(pA,   0, (size_t)N * sizeof(float));
    cudaMemsetAsync(pS,   0, (size_t)G * sizeof(float));
    cudaMemsetAsync(pcnt, 0, (size_t)G * sizeof(float));

    const int TB = 256;
    int nE4 = (E + 3) / 4;
    int gE4 = (nE4 + TB - 1) / TB;
    int gN  = (N + TB - 1) / TB;

    k_deg      <<<gE4, TB>>>(src, dst, E);
    k_x0       <<<gN,  TB>>>(N);
    k_scatter1 <<<gE4, TB>>>(src, dst, E);
    k_t        <<<gN,  TB>>>(N);
    k_scatter2 <<<gE4, TB>>>(src, dst, E);
    k_pool     <<<gN,  TB>>>(gid, N);
    k_final    <<<(G * 8 + TB - 1) / TB, TB>>>(W1, W2, Wlast, out, G);
}

// round 3
// speedup vs baseline: 1.2719x; 1.0344x over previous
#include <cuda_runtime.h>
#include <cstdint>

// Problem constants (fixed by the dataset)
#define NN 500000
#define GG 1000

// ---------------------------------------------------------------------------
// Scratch (device globals).
// g_deg[n]: lo32 = deg_in, hi32 = deg_out (packed).
// ---------------------------------------------------------------------------
__device__ unsigned long long g_deg [NN];
__device__ float              g_agg1[NN];   // layer-1 scalar aggregation
__device__ float              g_t   [NN];   // s * isi * iso (layer-2 propagand)
__device__ float              g_A   [NN];   // layer-2 scalar aggregation
__device__ float              g_S   [GG];   // pooled scalar sum per graph
__device__ float              g_cnt [GG];   // nodes per graph

#define ONE_IN  1ull
#define ONE_OUT (1ull << 32)

__device__ __forceinline__ void red_f32(float* p, float v) {
    asm volatile("red.global.add.f32 [%0], %1;" :: "l"(p), "f"(v) : "memory");
}
__device__ __forceinline__ void red_u64(unsigned long long* p, unsigned long long v) {
    asm volatile("red.global.add.u64 [%0], %1;" :: "l"(p), "l"(v) : "memory");
}

// ---------------------------------------------------------------------------
// K1: degree counting, packed u64. 8 edges / thread via 2x int4 loads.
// ---------------------------------------------------------------------------
__global__ void k_deg(const int* __restrict__ src, const int* __restrict__ dst, int E) {
    int i = blockIdx.x * blockDim.x + threadIdx.x;
    int base = i << 3;
    if (base + 7 < E) {
        int4 s0 = *reinterpret_cast<const int4*>(src + base);
        int4 s1 = *reinterpret_cast<const int4*>(src + base + 4);
        int4 d0 = *reinterpret_cast<const int4*>(dst + base);
        int4 d1 = *reinterpret_cast<const int4*>(dst + base + 4);
        red_u64(&g_deg[s0.x], ONE_OUT); red_u64(&g_deg[s0.y], ONE_OUT);
        red_u64(&g_deg[s0.z], ONE_OUT); red_u64(&g_deg[s0.w], ONE_OUT);
        red_u64(&g_deg[s1.x], ONE_OUT); red_u64(&g_deg[s1.y], ONE_OUT);
        red_u64(&g_deg[s1.z], ONE_OUT); red_u64(&g_deg[s1.w], ONE_OUT);
        red_u64(&g_deg[d0.x], ONE_IN);  red_u64(&g_deg[d0.y], ONE_IN);
        red_u64(&g_deg[d0.z], ONE_IN);  red_u64(&g_deg[d0.w], ONE_IN);
        red_u64(&g_deg[d1.x], ONE_IN);  red_u64(&g_deg[d1.y], ONE_IN);
        red_u64(&g_deg[d1.z], ONE_IN);  red_u64(&g_deg[d1.w], ONE_IN);
    } else {
        for (int e = base; e < E; ++e) {
            red_u64(&g_deg[src[e]], ONE_OUT);
            red_u64(&g_deg[dst[e]], ONE_IN);
        }
    }
}

// ---------------------------------------------------------------------------
// K2: layer-1 scatter with inline x0.
//     agg1[dst] += deg_in[src] * rsqrt(max(deg_out[src],1)).  8 edges/thread.
//     (8B random gather costs the same wavefront as 4B — sector-granular.)
// ---------------------------------------------------------------------------
__device__ __forceinline__ float x0_of(unsigned long long p) {
    float di = (float)(unsigned)p;
    float dq = (float)(unsigned)(p >> 32);
    return di * rsqrtf(fmaxf(dq, 1.0f));
}

__global__ void k_scatter1(const int* __restrict__ src, const int* __restrict__ dst, int E) {
    int i = blockIdx.x * blockDim.x + threadIdx.x;
    int base = i << 3;
    if (base + 7 < E) {
        int4 s0 = *reinterpret_cast<const int4*>(src + base);
        int4 s1 = *reinterpret_cast<const int4*>(src + base + 4);
        int4 d0 = *reinterpret_cast<const int4*>(dst + base);
        int4 d1 = *reinterpret_cast<const int4*>(dst + base + 4);
        float v0 = x0_of(__ldg(&g_deg[s0.x]));
        float v1 = x0_of(__ldg(&g_deg[s0.y]));
        float v2 = x0_of(__ldg(&g_deg[s0.z]));
        float v3 = x0_of(__ldg(&g_deg[s0.w]));
        float v4 = x0_of(__ldg(&g_deg[s1.x]));
        float v5 = x0_of(__ldg(&g_deg[s1.y]));
        float v6 = x0_of(__ldg(&g_deg[s1.z]));
        float v7 = x0_of(__ldg(&g_deg[s1.w]));
        red_f32(&g_agg1[d0.x], v0); red_f32(&g_agg1[d0.y], v1);
        red_f32(&g_agg1[d0.z], v2); red_f32(&g_agg1[d0.w], v3);
        red_f32(&g_agg1[d1.x], v4); red_f32(&g_agg1[d1.y], v5);
        red_f32(&g_agg1[d1.z], v6); red_f32(&g_agg1[d1.w], v7);
    } else {
        for (int e = base; e < E; ++e)
            red_f32(&g_agg1[dst[e]], x0_of(__ldg(&g_deg[src[e]])));
    }
}

// ---------------------------------------------------------------------------
// K3: t[n] = agg1[n] * isi[n] * iso[n]; also zeroes A and the pool buffers.
// ---------------------------------------------------------------------------
__global__ void k_t(int N) {
    int i = blockIdx.x * blockDim.x + threadIdx.x;
    if (i < GG) { g_S[i] = 0.0f; g_cnt[i] = 0.0f; }
    if (i >= N) return;
    unsigned long long p = g_deg[i];
    float isi = rsqrtf(fmaxf((float)(unsigned)p, 1.0f));
    float iso = rsqrtf(fmaxf((float)(unsigned)(p >> 32), 1.0f));
    g_t[i] = g_agg1[i] * isi * iso;
    g_A[i] = 0.0f;
}

// ---------------------------------------------------------------------------
// K4: layer-2 scalar scatter  A[dst] += t[src].  8 edges/thread.
// ---------------------------------------------------------------------------
__global__ void k_scatter2(const int* __restrict__ src, const int* __restrict__ dst, int E) {
    int i = blockIdx.x * blockDim.x + threadIdx.x;
    int base = i << 3;
    if (base + 7 < E) {
        int4 s0 = *reinterpret_cast<const int4*>(src + base);
        int4 s1 = *reinterpret_cast<const int4*>(src + base + 4);
        int4 d0 = *reinterpret_cast<const int4*>(dst + base);
        int4 d1 = *reinterpret_cast<const int4*>(dst + base + 4);
        float v0 = __ldg(&g_t[s0.x]);
        float v1 = __ldg(&g_t[s0.y]);
        float v2 = __ldg(&g_t[s0.z]);
        float v3 = __ldg(&g_t[s0.w]);
        float v4 = __ldg(&g_t[s1.x]);
        float v5 = __ldg(&g_t[s1.y]);
        float v6 = __ldg(&g_t[s1.z]);
        float v7 = __ldg(&g_t[s1.w]);
        red_f32(&g_A[d0.x], v0); red_f32(&g_A[d0.y], v1);
        red_f32(&g_A[d0.z], v2); red_f32(&g_A[d0.w], v3);
        red_f32(&g_A[d1.x], v4); red_f32(&g_A[d1.y], v5);
        red_f32(&g_A[d1.z], v6); red_f32(&g_A[d1.w], v7);
    } else {
        for (int e = base; e < E; ++e)
            red_f32(&g_A[dst[e]], __ldg(&g_t[src[e]]));
    }
}

// ---------------------------------------------------------------------------
// K5: scalar pooling.  u = A * isi;  S[g] += u; cnt[g] += 1.
//     graph_ids sorted -> warp-uniform fast path (2 REDs per warp).
// ---------------------------------------------------------------------------
__global__ void k_pool(const int* __restrict__ gid, int N) {
    int i = blockIdx.x * blockDim.x + threadIdx.x;
    bool valid = (i < N);
    float u = 0.0f;
    int g = -1;
    if (valid) {
        unsigned long long p = g_deg[i];
        u = g_A[i] * rsqrtf(fmaxf((float)(unsigned)p, 1.0f));
        g = gid[i];
    }
    int  g0  = __shfl_sync(0xffffffffu, g, 0);
    bool uni = __all_sync(0xffffffffu, valid && (g == g0));
    if (uni) {
#pragma unroll
        for (int o = 16; o > 0; o >>= 1)
            u += __shfl_xor_sync(0xffffffffu, u, o);
        if ((threadIdx.x & 31) == 0) {
            red_f32(&g_S[g0], u);
            red_f32(&g_cnt[g0], 32.0f);
        }
    } else if (valid) {
        red_f32(&g_S[g], u);
        red_f32(&g_cnt[g], 1.0f);
    }
}

// ---------------------------------------------------------------------------
// K6: out[g][c] = (S_g / max(cnt_g,1)) * rW_c
//     rW_c = relu(relu(W1) @ W2) @ Wlast[:,c]
// ---------------------------------------------------------------------------
__global__ void k_final(const float* __restrict__ W1, const float* __restrict__ W2,
                        const float* __restrict__ Wlast, float* __restrict__ out, int G) {
    int t = blockIdx.x * blockDim.x + threadIdx.x;
    if (t >= G * 8) return;
    int g = t >> 3;
    int c = t & 7;
    float rw = 0.0f;
#pragma unroll
    for (int k = 0; k < 8; ++k) {
        float q = 0.0f;
#pragma unroll
        for (int j = 0; j < 8; ++j)
            q += fmaxf(__ldg(&W1[j]), 0.0f) * __ldg(&W2[j * 8 + k]);
        rw += fmaxf(q, 0.0f) * __ldg(&Wlast[k * 8 + c]);
    }
    out[t] = (g_S[g] / fmaxf(g_cnt[g], 1.0f)) * rw;
}

// ---------------------------------------------------------------------------
// kernel_launch — graph-capturable, allocation-free.
// Inputs (metadata order): W1[8], W2[64], Wlast[64], src[E], dst[E], graph_ids[N]
// Output: G*C float32
// ---------------------------------------------------------------------------
extern "C" void kernel_launch(void* const* d_in, const int* in_sizes, int n_in,
                              void* d_out, int out_size) {
    const float* W1    = (const float*)d_in[0];
    const float* W2    = (const float*)d_in[1];
    const float* Wlast = (const float*)d_in[2];
    const int*   src   = (const int*)d_in[3];
    const int*   dst   = (const int*)d_in[4];
    const int*   gid   = (const int*)d_in[5];

    int E = in_sizes[3];
    int N = in_sizes[5];
    int G = out_size / 8;
    float* out = (float*)d_out;

    void *pdeg, *pa1;
    cudaGetSymbolAddress(&pdeg, g_deg);
    cudaGetSymbolAddress(&pa1,  g_agg1);
    cudaMemsetAsync(pdeg, 0, (size_t)N * sizeof(unsigned long long));
    cudaMemsetAsync(pa1,  0, (size_t)N * sizeof(float));

    const int TB = 256;
    int nE8 = (E + 7) / 8;
    int gE8 = (nE8 + TB - 1) / TB;
    int gN  = (N + TB - 1) / TB;

    k_deg      <<<gE8, TB>>>(src, dst, E);
    k_scatter1 <<<gE8, TB>>>(src, dst, E);
    k_t        <<<gN,  TB>>>(N);
    k_scatter2 <<<gE8, TB>>>(src, dst, E);
    k_pool     <<<gN,  TB>>>(gid, N);
    k_final    <<<(G * 8 + TB - 1) / TB, TB>>>(W1, W2, Wlast, out, G);
}